// round 15
// baseline (speedup 1.0000x reference)
#include <cuda_runtime.h>
#include <cuda_bf16.h>
#include <cstddef>

// Problem constants (fixed by the reference setup)
constexpr int B   = 16;
constexpr int TM  = 128;
constexpr int SM_ = 64;
constexpr int SP1 = SM_ + 1;           // 65
constexpr int ST  = 66;                // padded stride (even -> float2-aligned)
constexpr int V   = 1024;
constexpr int NROWS = B * TM * SP1;    // 133120 logical rows
constexpr int SCR   = B * TM * ST;     // scratch elements per array

// Scratch in EXP space, padded stride-66 layout: idx = b*TM*ST + t*ST + s.
// Re-initialized to SENTINEL by init_kernel at the start of every run.
__device__ float g_eb[SCR];
__device__ float g_el[SCR];

#define SENTINEL_BITS 0xBF800000u      // -1.0f ; eb in (0,1], el in [0,1)

__device__ __forceinline__ void stcg(float* p, float v) {
    asm volatile("st.global.cg.f32 [%0], %1;" :: "l"(p), "f"(v) : "memory");
}
__device__ __forceinline__ float ldcg(const float* p) {
    float v;
    asm volatile("ld.global.cg.f32 %0, [%1];" : "=f"(v) : "l"(p) : "memory");
    return v;
}
__device__ __forceinline__ float2 ldcg2(const float2* p) {
    float2 v;
    asm volatile("ld.global.cg.v2.f32 {%0,%1}, [%2];"
                 : "=f"(v.x), "=f"(v.y) : "l"(p) : "memory");
    return v;
}

// ---------------------------------------------------------------------------
// Init: fill scratch with sentinel. Runs before the fused kernel each replay.
// ---------------------------------------------------------------------------
__global__ void __launch_bounds__(256)
init_kernel()
{
    const float s = __int_as_float(SENTINEL_BITS);
    const float4 s4 = make_float4(s, s, s, s);
    const int i = blockIdx.x * blockDim.x + threadIdx.x;
    // SCR = 135168, divisible by 4 (ST even)
    if (i < SCR / 4) {
        reinterpret_cast<float4*>(g_eb)[i] = s4;
        reinterpret_cast<float4*>(g_el)[i] = s4;
    }
}

// ---------------------------------------------------------------------------
// Fused producer/consumer kernel.
//   blocks [0, B)  : alpha consumer, one warp per batch (blocks 0..15 land in
//                    wave 1 -> co-resident with producers from the start).
//   blocks [B, ..) : lse producer, 8 rows per CTA (one warp per row).
// Sync = data-as-ready sentinels: producer stcg's results; consumer ldcg-polls
// exactly the words it needs. No fences, no atomics, no counters.
// __launch_bounds__(256, 6): caps regs (~42) so producer occupancy stays high.
// ---------------------------------------------------------------------------
__global__ void __launch_bounds__(256, 6)
rnnt_fused_kernel(const float* __restrict__ acts,
                  const int*   __restrict__ labels,
                  const int*   __restrict__ input_lengths,
                  const int*   __restrict__ label_lengths,
                  float*       __restrict__ out)
{
    // =========================== PRODUCER ROLE ===========================
    if (blockIdx.x >= B) {
        const int row  = (blockIdx.x - B) * 8 + (threadIdx.x >> 5);
        const int lane = threadIdx.x & 31;
        if (row >= NROWS) return;

        const float4* p = reinterpret_cast<const float4*>(acts)
                        + (size_t)row * (V / 4);
        float4 v[8];
#pragma unroll
        for (int j = 0; j < 8; j++) v[j] = p[j * 32 + lane];

        float m = v[0].x;
#pragma unroll
        for (int j = 0; j < 8; j++)
            m = fmaxf(m, fmaxf(fmaxf(v[j].x, v[j].y), fmaxf(v[j].z, v[j].w)));
        float s = 0.f;
#pragma unroll
        for (int j = 0; j < 8; j++)
            s += __expf(v[j].x - m) + __expf(v[j].y - m)
               + __expf(v[j].z - m) + __expf(v[j].w - m);
#pragma unroll
        for (int off = 16; off > 0; off >>= 1) {
            float mo = __shfl_xor_sync(0xffffffffu, m, off);
            float so = __shfl_xor_sync(0xffffffffu, s, off);
            float M  = fmaxf(m, mo);
            s = s * __expf(m - M) + so * __expf(mo - M);
            m = M;
        }

        if (lane == 0) {
            const float lse = m + __logf(s);
            const int b    = row / (TM * SP1);
            const int rem  = row % (TM * SP1);
            const int tt   = rem / SP1;
            const int sidx = rem % SP1;
            const int oidx = b * TM * ST + tt * ST + sidx;

            float el = 0.f;
            if (sidx < SM_) {
                const int lab = labels[b * SM_ + sidx];
                el = __expf(__ldg(acts + (size_t)row * V + lab) - lse); // L1 hit
            }
            stcg(&g_eb[oidx], __expf(v[0].x - lse));
            stcg(&g_el[oidx], el);
        }
        return;
    }

    // =========================== CONSUMER ROLE ===========================
    if (threadIdx.x >= 32) return;                   // one warp per batch
    const int b = blockIdx.x;
    const int l = threadIdx.x;
    const unsigned FULL = 0xffffffffu;

    const int Tb = input_lengths[b];
    const int Sb = label_lengths[b];

    const float* __restrict__ ebb = g_eb + (size_t)b * TM * ST;
    const float* __restrict__ elb = g_el + (size_t)b * TM * ST;

    float x   = (l == 0) ? 1.f : 0.f;    // A[2l]
    float y   = 0.f;                     // A[2l+1]
    float top = 0.f;                     // A[64]; valid in lane 31 only
    float C   = 0.f;                     // accumulated log scale

    constexpr float THR   = 0x1p-24f;
    constexpr float SCALE = 0x1p64f;
    constexpr float LN_SC = 44.3614195558364998f;   // 64*ln(2)
    const float SEN = __int_as_float(SENTINEL_BITS);

    for (int t = 0; t < Tb; t++) {
        const float* bt = ebb + t * ST;
        const float* lt = elb + t * ST;

        // Poll-load this step's operands until the producer has written them.
        float2 eb2, el2;
        float  ebt, elt;
        {
            unsigned ns = 32;
            for (;;) {
                eb2 = ldcg2(reinterpret_cast<const float2*>(bt + 2 * l));
                el2 = ldcg2(reinterpret_cast<const float2*>(lt + 2 * l));
                ebt = ldcg(bt + 64);
                elt = ldcg(lt + 63);
                const bool ok = (eb2.x != SEN) & (eb2.y != SEN)
                              & (el2.x != SEN) & (el2.y != SEN)
                              & (ebt  != SEN) & (elt  != SEN);
                if (__all_sync(FULL, ok)) break;
                __nanosleep(ns);
                if (ns < 1024) ns <<= 1;
            }
        }

        const float s_  = __shfl_up_sync(FULL, el2.y, 1);
        const float em1 = l ? s_ : 0.f;              // el[2l-1]
        const float py  = __shfl_up_sync(FULL, y, 1); // A[2l-1]
        const float nx  = fmaf(py, em1, x * eb2.x);
        const float ny  = fmaf(x, el2.x, y * eb2.y);
        top = fmaf(y, elt, top * ebt);               // lane31: y == A[63]
        x = nx;  y = ny;

        if ((t & 3) == 3) {                          // proven 4-step cadence
            float Ml = fmaxf(x, y);
            if (l == 31) Ml = fmaxf(Ml, top);
            if (__all_sync(FULL, Ml < THR)) {
                x *= SCALE;  y *= SCALE;  top *= SCALE;  C -= LN_SC;
            }
        }
    }

    // select A[Sb]:  Sb==64 -> top (lane 31) ; else lane Sb/2, comp Sb%2
    float res;
    if (Sb >= 64) res = __shfl_sync(FULL, top, 31);
    else          res = __shfl_sync(FULL, (Sb & 1) ? y : x, Sb >> 1);

    if (l == 0) out[b] = -(C + __logf(res));
}

// ---------------------------------------------------------------------------
extern "C" void kernel_launch(void* const* d_in, const int* in_sizes, int n_in,
                              void* d_out, int out_size)
{
    const float* acts   = (const float*)d_in[0];
    const int*   labels = (const int*)d_in[1];
    const int*   ilen   = (const int*)d_in[2];
    const int*   llen   = (const int*)d_in[3];
    float*       out    = (float*)d_out;

    // 1) reset scratch to sentinel (ordered before the fused kernel on the
    //    same stream; both launches are graph-capturable)
    const int initN = SCR / 4;
    init_kernel<<<(initN + 255) / 256, 256>>>();

    // 2) fused producer/consumer
    const int producer_ctas = (NROWS + 7) / 8;       // 16640
    rnnt_fused_kernel<<<B + producer_ctas, 256>>>(acts, labels, ilen, llen, out);
}